// round 13
// baseline (speedup 1.0000x reference)
#include <cuda_runtime.h>

// Differential box-counting fractal dimension, 512x512 f32, 64x64 windows
// stride 4 -> 113x113. One block per OUTPUT ROW (113 blocks = one wave).
// 3 phases / 2 barriers:
//   P1: packed (max,min) 4x4-pixel-tile grid D0 (16x128), 2x4 batched loads
//   B : cs1 2-way partials (16ld, 256thr) | cs2 4-way partials (16ld, 512thr)
//       | V3 8-row halves (8ld, 256thr) which ALSO emit the level-4 column
//         diff partial sums pcs0 (cs0 branch eliminated)
//   P6: windows split across intra-warp thread pairs, one shfl_xor combine.

#define OH 113

__global__ __launch_bounds__(1024, 1)
void fd_kernel(const float* __restrict__ img, float* __restrict__ out)
{
    __shared__ float2 D0[16][128];   // (max, min) per 4x4 pixel tile
    __shared__ float2 pcs0[128];     // level-4 column diff partials (.x: rows0-7, .y: rows8-15)
    __shared__ float  cs1p[2][128];  // level-8 column partials (a=4h..4h+3)
    __shared__ float  cs2p[4][128];  // level-16 column partials (one a-block)
    __shared__ float4 V3b[128];      // (max0,min0,max1,min1): vertical 8-row halves

    const int tid = threadIdx.x;
    const int gi  = blockIdx.x;      // output row 0..112
    const int R0  = 4 * gi;

    // ---- P1: 4x4 pixel-tile max/min, 2 tiles/thread, two 4-load batches ----
    {
        const int r = tid >> 7, c = tid & 127;
        const float* pA = img + (R0 + 4 * r) * 512 + 4 * c;
        {
            float4 v0 = *reinterpret_cast<const float4*>(pA);
            float4 v1 = *reinterpret_cast<const float4*>(pA + 512);
            float4 v2 = *reinterpret_cast<const float4*>(pA + 1024);
            float4 v3 = *reinterpret_cast<const float4*>(pA + 1536);
            float mx = fmaxf(fmaxf(v0.x, v0.y), fmaxf(v0.z, v0.w));
            float mn = fminf(fminf(v0.x, v0.y), fminf(v0.z, v0.w));
            mx = fmaxf(mx, fmaxf(fmaxf(v1.x, v1.y), fmaxf(v1.z, v1.w)));
            mn = fminf(mn, fminf(fminf(v1.x, v1.y), fminf(v1.z, v1.w)));
            mx = fmaxf(mx, fmaxf(fmaxf(v2.x, v2.y), fmaxf(v2.z, v2.w)));
            mn = fminf(mn, fminf(fminf(v2.x, v2.y), fminf(v2.z, v2.w)));
            mx = fmaxf(mx, fmaxf(fmaxf(v3.x, v3.y), fmaxf(v3.z, v3.w)));
            mn = fminf(mn, fminf(fminf(v3.x, v3.y), fminf(v3.z, v3.w)));
            D0[r][c] = make_float2(mx, mn);
        }
        const float* pB = pA + 32 * 512;
        {
            float4 v0 = *reinterpret_cast<const float4*>(pB);
            float4 v1 = *reinterpret_cast<const float4*>(pB + 512);
            float4 v2 = *reinterpret_cast<const float4*>(pB + 1024);
            float4 v3 = *reinterpret_cast<const float4*>(pB + 1536);
            float mx = fmaxf(fmaxf(v0.x, v0.y), fmaxf(v0.z, v0.w));
            float mn = fminf(fminf(v0.x, v0.y), fminf(v0.z, v0.w));
            mx = fmaxf(mx, fmaxf(fmaxf(v1.x, v1.y), fmaxf(v1.z, v1.w)));
            mn = fminf(mn, fminf(fminf(v1.x, v1.y), fminf(v1.z, v1.w)));
            mx = fmaxf(mx, fmaxf(fmaxf(v2.x, v2.y), fmaxf(v2.z, v2.w)));
            mn = fminf(mn, fminf(fminf(v2.x, v2.y), fminf(v2.z, v2.w)));
            mx = fmaxf(mx, fmaxf(fmaxf(v3.x, v3.y), fmaxf(v3.z, v3.w)));
            mn = fminf(mn, fminf(fminf(v3.x, v3.y), fminf(v3.z, v3.w)));
            D0[r + 8][c] = make_float2(mx, mn);
        }
    }
    __syncthreads();

    // ---- Phase B: cs1 (256) | cs2 (512) | V3 + pcs0 (256) ----
    if (tid < 256) {
        // cs1p[h][c]: 4 of 8 2x2-blocks (a = 4h..4h+3)        [16 loads]
        const int h = tid >> 7, c = tid & 127;
        if (c < 127) {
            float s = 0.f;
            #pragma unroll
            for (int aa = 0; aa < 4; aa++) {
                const int a = 4 * h + aa;
                const float2 v00 = D0[2*a][c],   v01 = D0[2*a][c+1];
                const float2 v10 = D0[2*a+1][c], v11 = D0[2*a+1][c+1];
                s += fmaxf(fmaxf(v00.x, v01.x), fmaxf(v10.x, v11.x))
                   - fminf(fminf(v00.y, v01.y), fminf(v10.y, v11.y));
            }
            cs1p[h][c] = s;
        }
    } else if (tid < 768) {
        // cs2p[a][c]: one 4x4 block diff                      [16 loads]
        const int idx = tid - 256;
        const int a = idx >> 7, c = idx & 127;
        if (c < 125) {
            const int rb = 4 * a;
            float m = -3.0e38f, n = 3.0e38f;
            #pragma unroll
            for (int dr = 0; dr < 4; dr++) {
                const float2 a0 = D0[rb+dr][c],   a1 = D0[rb+dr][c+1];
                const float2 a2 = D0[rb+dr][c+2], a3 = D0[rb+dr][c+3];
                m = fmaxf(m, fmaxf(fmaxf(a0.x, a1.x), fmaxf(a2.x, a3.x)));
                n = fminf(n, fminf(fminf(a0.y, a1.y), fminf(a2.y, a3.y)));
            }
            cs2p[a][c] = m - n;
        }
    } else {
        // V3 half j: vertical 8-row max/min + level-4 diff partial  [8 loads]
        const int idx = tid - 768;
        const int j = idx >> 7, c = idx & 127;
        float m = -3.0e38f, n = 3.0e38f, s = 0.f;
        #pragma unroll
        for (int dr = 0; dr < 8; dr++) {
            const float2 v = D0[8*j + dr][c];
            m = fmaxf(m, v.x);
            n = fminf(n, v.y);
            s += v.x - v.y;
        }
        reinterpret_cast<float2*>(&V3b[c])[j] = make_float2(m, n);
        reinterpret_cast<float*>(&pcs0[c])[j] = s;
    }
    __syncthreads();

    // ---- P6: 2 threads per window (intra-warp pair), shfl combine ----
    if (tid < 2 * OH) {
        const int wj = tid >> 1;         // window 0..112
        const int h  = tid & 1;          // half id (pair lanes adjacent)
        float part;

        if (h == 0) {
            float d4 = 0.f, d8 = 0.f;
            #pragma unroll
            for (int t = 0; t < 16; t++) {
                const float2 p = pcs0[wj + t];
                d4 += p.x + p.y;
            }
            #pragma unroll
            for (int b = 0; b < 8; b++) {
                const int c = wj + 2 * b;
                d8 += cs1p[0][c] + cs1p[1][c];
            }
            part = 2.07944154168f * __logf(d8) + 1.38629436112f * __logf(d4);
        } else {
            float d16 = 0.f;
            #pragma unroll
            for (int b = 0; b < 4; b++) {
                const int c = wj + 4 * b;
                d16 += cs2p[0][c] + cs2p[1][c] + cs2p[2][c] + cs2p[3][c];
            }
            float d32 = 0.f, gm = -3.0e38f, gn = 3.0e38f;
            #pragma unroll
            for (int k = 0; k < 2; k++) {
                float m0 = -3.0e38f, n0 = 3.0e38f, m1 = -3.0e38f, n1 = 3.0e38f;
                #pragma unroll
                for (int t = 0; t < 8; t++) {
                    const float4 v = V3b[wj + 8 * k + t];
                    m0 = fmaxf(m0, v.x);  n0 = fminf(n0, v.y);
                    m1 = fmaxf(m1, v.z);  n1 = fminf(n1, v.w);
                }
                d32 += (m0 - n0) + (m1 - n1);
                gm = fmaxf(gm, fmaxf(m0, m1));
                gn = fminf(gn, fminf(n0, n1));
            }
            const float d64 = gm - gn;
            part = 4.15888308336f * __logf(d64) + 3.46573590280f * __logf(d32)
                 + 2.77258872224f * __logf(d16);
        }

        const float other = __shfl_xor_sync(0xffffffffu, part, 1);
        if (h == 0) {
            const float S2 = 4.15888308336f*4.15888308336f
                           + 3.46573590280f*3.46573590280f
                           + 2.77258872224f*2.77258872224f
                           + 2.07944154168f*2.07944154168f
                           + 1.38629436112f*1.38629436112f;
            out[gi * OH + wj] = -(part + other) / S2;
        }
    }
}

extern "C" void kernel_launch(void* const* d_in, const int* in_sizes, int n_in,
                              void* d_out, int out_size)
{
    const float* img = (const float*)d_in[0];   // (1,1,512,512) f32
    float* out = (float*)d_out;                 // (1,1,113,113) f32
    fd_kernel<<<OH, 1024>>>(img, out);
}